// round 1
// baseline (speedup 1.0000x reference)
#include <cuda_runtime.h>
#include <math.h>

// AttentionST: attention pooling, single pass over embeddings.
// E: [B, S, D] fp32, w_att: [D], w_pred: [D], b_pred: scalar -> out: [B]
// logit[b] = sum_s softmax(E[b]·w_att)[s] * (E[b,s]·w_pred) + b_pred; out = sigmoid(logit)

constexpr int D = 768;
constexpr int S = 512;
constexpr int NTHREADS = 256;
constexpr int NWARPS = NTHREADS / 32;
constexpr int F4_PER_ROW = D / 4;        // 192
constexpr int F4_PER_LANE = F4_PER_ROW / 32;  // 6

__global__ __launch_bounds__(NTHREADS, 2) void attn_pool_kernel(
    const float* __restrict__ E,
    const float* __restrict__ w_att,
    const float* __restrict__ w_pred,
    const float* __restrict__ b_pred,
    float* __restrict__ out)
{
    __shared__ float s_t[S];          // attention scores
    __shared__ float s_p[S];          // per-position pred dot products
    __shared__ float red[2 * NWARPS];

    const int b    = blockIdx.x;
    const int tid  = threadIdx.x;
    const int warp = tid >> 5;
    const int lane = tid & 31;

    // Cache each lane's fixed slices of the weight vectors in registers.
    float4 wa[F4_PER_LANE], wp[F4_PER_LANE];
    #pragma unroll
    for (int j = 0; j < F4_PER_LANE; j++) {
        wa[j] = reinterpret_cast<const float4*>(w_att)[j * 32 + lane];
        wp[j] = reinterpret_cast<const float4*>(w_pred)[j * 32 + lane];
    }

    const float4* Eb = reinterpret_cast<const float4*>(E) + (size_t)b * S * F4_PER_ROW;

    // Pass 1: per-row dual dot products. Warp w handles s = w, w+8, ...
    for (int s = warp; s < S; s += NWARPS) {
        const float4* row = Eb + (size_t)s * F4_PER_ROW;
        float t = 0.f, p = 0.f;
        #pragma unroll
        for (int j = 0; j < F4_PER_LANE; j++) {
            float4 v = row[j * 32 + lane];
            t = fmaf(v.x, wa[j].x, t); t = fmaf(v.y, wa[j].y, t);
            t = fmaf(v.z, wa[j].z, t); t = fmaf(v.w, wa[j].w, t);
            p = fmaf(v.x, wp[j].x, p); p = fmaf(v.y, wp[j].y, p);
            p = fmaf(v.z, wp[j].z, p); p = fmaf(v.w, wp[j].w, p);
        }
        #pragma unroll
        for (int o = 16; o; o >>= 1) {
            t += __shfl_xor_sync(0xffffffffu, t, o);
            p += __shfl_xor_sync(0xffffffffu, p, o);
        }
        if (lane == 0) { s_t[s] = t; s_p[s] = p; }
    }
    __syncthreads();

    // Pass 2: softmax max over scores.
    float m = -INFINITY;
    for (int s = tid; s < S; s += NTHREADS) m = fmaxf(m, s_t[s]);
    #pragma unroll
    for (int o = 16; o; o >>= 1) m = fmaxf(m, __shfl_xor_sync(0xffffffffu, m, o));
    if (lane == 0) red[warp] = m;
    __syncthreads();
    if (warp == 0) {
        float mm = (lane < NWARPS) ? red[lane] : -INFINITY;
        #pragma unroll
        for (int o = 16; o; o >>= 1) mm = fmaxf(mm, __shfl_xor_sync(0xffffffffu, mm, o));
        if (lane == 0) red[0] = mm;
    }
    __syncthreads();
    m = red[0];

    // Pass 3: sum of exp and exp-weighted p.
    float se = 0.f, sep = 0.f;
    for (int s = tid; s < S; s += NTHREADS) {
        float e = expf(s_t[s] - m);
        se  += e;
        sep += e * s_p[s];
    }
    #pragma unroll
    for (int o = 16; o; o >>= 1) {
        se  += __shfl_xor_sync(0xffffffffu, se, o);
        sep += __shfl_xor_sync(0xffffffffu, sep, o);
    }
    __syncthreads();  // everyone has read red[0] before we overwrite
    if (lane == 0) { red[warp] = se; red[NWARPS + warp] = sep; }
    __syncthreads();
    if (tid == 0) {
        float tse = 0.f, tsep = 0.f;
        #pragma unroll
        for (int w = 0; w < NWARPS; w++) { tse += red[w]; tsep += red[NWARPS + w]; }
        float logit = tsep / tse + b_pred[0];
        out[b] = 1.f / (1.f + expf(-logit));
    }
}

extern "C" void kernel_launch(void* const* d_in, const int* in_sizes, int n_in,
                              void* d_out, int out_size)
{
    const float* E      = (const float*)d_in[0];
    const float* w_att  = (const float*)d_in[1];
    const float* w_pred = (const float*)d_in[2];
    const float* b_pred = (const float*)d_in[3];
    float* out = (float*)d_out;

    const int B = in_sizes[0] / (S * D);
    attn_pool_kernel<<<B, NTHREADS>>>(E, w_att, w_pred, b_pred, out);
}